// round 1
// baseline (speedup 1.0000x reference)
#include <cuda_runtime.h>
#include <cuda_bf16.h>

// Problem constants (fixed-shape problem)
#define NNODES 50000
#define NEDGES 800000
#define NGRAPHS 256
#define HID 100
#define K1 336
#define NOUT 29

// Scratch (device globals — allocation-free rule)
__device__ float g_yrel[NNODES * HID];
__device__ float g_buf0[NNODES * HID];
__device__ float g_buf1[NNODES * HID];
__device__ float g_pool[NGRAPHS * HID];
__device__ float g_m1[NGRAPHS * HID];
__device__ float g_m2[NGRAPHS * HID];

// ---------------------------------------------------------------------------
// Dual GEMM: for each node row i of A [Nrows, K]:
//   Yrel[i,:] = act(A[i,:]) @ Wrel.T           (blockIdx.y == 0)
//   Agg [i,:] = act(A[i,:]) @ Wroot.T + bias   (blockIdx.y == 1)
// act = relu if applyRelu (folds previous layer's relu into the load).
// W matrices are [HID, K] row-major. N padded to 128 internally.
// ---------------------------------------------------------------------------
#define BM 64
#define BN 128
#define BK 16

__global__ __launch_bounds__(256) void gemm_dual(
    const float* __restrict__ A, int Nrows, int K,
    const float* __restrict__ Wrel, const float* __restrict__ Wroot,
    const float* __restrict__ bias,
    float* __restrict__ Yrel, float* __restrict__ Agg, int applyRelu)
{
    const float* W = blockIdx.y ? Wroot : Wrel;
    float* O = blockIdx.y ? Agg : Yrel;
    const int addB = blockIdx.y;

    __shared__ float As[BK][BM];
    __shared__ float Bs[BK][BN];

    const int tid = threadIdx.x;
    const int tx = tid & 15;   // n-group (8 cols each)
    const int ty = tid >> 4;   // m-group (4 rows each)
    const int row0 = blockIdx.x * BM;

    float acc[4][8];
#pragma unroll
    for (int i = 0; i < 4; i++)
#pragma unroll
        for (int j = 0; j < 8; j++) acc[i][j] = 0.f;

    for (int k0 = 0; k0 < K; k0 += BK) {
        // Load A tile: 64 rows x 16 k. Each thread: one float4.
        {
            int m = tid >> 2;
            int kq = (tid & 3) * 4;
            int r = row0 + m;
            float4 v = make_float4(0.f, 0.f, 0.f, 0.f);
            if (r < Nrows && (k0 + kq + 3) < K)
                v = *(const float4*)(A + (size_t)r * K + k0 + kq);
            if (applyRelu) {
                v.x = fmaxf(v.x, 0.f); v.y = fmaxf(v.y, 0.f);
                v.z = fmaxf(v.z, 0.f); v.w = fmaxf(v.w, 0.f);
            }
            As[kq + 0][m] = v.x; As[kq + 1][m] = v.y;
            As[kq + 2][m] = v.z; As[kq + 3][m] = v.w;
        }
        // Load W tile transposed: Bs[k][n] = W[n, k0+k], n in [0,128), guard n<HID
        {
#pragma unroll
            for (int p = 0; p < 2; p++) {
                int n = (tid >> 2) + p * 64;
                int kq = (tid & 3) * 4;
                float4 v = make_float4(0.f, 0.f, 0.f, 0.f);
                if (n < HID && (k0 + kq + 3) < K)
                    v = *(const float4*)(W + (size_t)n * K + k0 + kq);
                Bs[kq + 0][n] = v.x; Bs[kq + 1][n] = v.y;
                Bs[kq + 2][n] = v.z; Bs[kq + 3][n] = v.w;
            }
        }
        __syncthreads();

#pragma unroll
        for (int k = 0; k < BK; k++) {
            float a[4], b[8];
#pragma unroll
            for (int i = 0; i < 4; i++) a[i] = As[k][ty * 4 + i];
#pragma unroll
            for (int j = 0; j < 8; j++) b[j] = Bs[k][tx * 8 + j];
#pragma unroll
            for (int i = 0; i < 4; i++)
#pragma unroll
                for (int j = 0; j < 8; j++) acc[i][j] += a[i] * b[j];
        }
        __syncthreads();
    }

#pragma unroll
    for (int i = 0; i < 4; i++) {
        int r = row0 + ty * 4 + i;
        if (r >= Nrows) continue;
#pragma unroll
        for (int j = 0; j < 8; j++) {
            int n = tx * 8 + j;
            if (n < HID) {
                float v = acc[i][j];
                if (addB) v += bias[n];
                O[(size_t)r * HID + n] = v;
            }
        }
    }
}

// ---------------------------------------------------------------------------
// Edge scatter: agg[dst,:] += yrel[src,:]  — warp per edge, red.v4 atomics.
// ---------------------------------------------------------------------------
__global__ __launch_bounds__(256) void scatter_edges(
    const int* __restrict__ src, const int* __restrict__ dst,
    const float* __restrict__ yrel, float* __restrict__ agg)
{
    int warp = (blockIdx.x * blockDim.x + threadIdx.x) >> 5;
    int lane = threadIdx.x & 31;
    if (warp >= NEDGES) return;
    int s = src[warp];
    int d = dst[warp];
    if (lane < HID / 4) {
        const float4* yp = (const float4*)(yrel + (size_t)s * HID);
        float4 v = yp[lane];
        float4* ap = (float4*)(agg + (size_t)d * HID) + lane;
        asm volatile("red.global.add.v4.f32 [%0], {%1,%2,%3,%4};"
                     :: "l"(ap), "f"(v.x), "f"(v.y), "f"(v.z), "f"(v.w)
                     : "memory");
    }
}

// ---------------------------------------------------------------------------
// Mean pool over sorted batch: block per graph, binary search for range.
// Applies relu to the last conv output on the fly.
// ---------------------------------------------------------------------------
__device__ __forceinline__ int lower_bound_i(const int* a, int n, int key) {
    int lo = 0, hi = n;
    while (lo < hi) {
        int mid = (lo + hi) >> 1;
        if (a[mid] < key) lo = mid + 1; else hi = mid;
    }
    return lo;
}

__global__ __launch_bounds__(128) void pool_kernel(
    const float* __restrict__ h, const int* __restrict__ batch,
    float* __restrict__ pooled)
{
    int g = blockIdx.x;
    __shared__ int s_se[2];
    if (threadIdx.x == 0) {
        s_se[0] = lower_bound_i(batch, NNODES, g);
        s_se[1] = lower_bound_i(batch, NNODES, g + 1);
    }
    __syncthreads();
    int start = s_se[0], end = s_se[1];
    int c = threadIdx.x;
    if (c < HID) {
        float s = 0.f;
        for (int i = start; i < end; i++)
            s += fmaxf(h[(size_t)i * HID + c], 0.f);
        float cnt = (float)((end - start) > 0 ? (end - start) : 1);
        pooled[g * HID + c] = s / cnt;
    }
}

// ---------------------------------------------------------------------------
// Small MLP layer: out[g, c] = (relu?)(in[g,:] @ W[c,:] + b[c])
// ---------------------------------------------------------------------------
__global__ __launch_bounds__(128) void mlp_kernel(
    const float* __restrict__ in, const float* __restrict__ W,
    const float* __restrict__ bv, float* __restrict__ out,
    int Kin, int Nout, int doRelu)
{
    int g = blockIdx.x;
    __shared__ float sin_[128];
    if (threadIdx.x < Kin) sin_[threadIdx.x] = in[g * Kin + threadIdx.x];
    __syncthreads();
    int c = threadIdx.x;
    if (c < Nout) {
        float s = bv[c];
        const float* wr = W + (size_t)c * Kin;
        for (int k = 0; k < Kin; k++) s = fmaf(sin_[k], wr[k], s);
        if (doRelu) s = fmaxf(s, 0.f);
        out[g * Nout + c] = s;
    }
}

// ---------------------------------------------------------------------------
extern "C" void kernel_launch(void* const* d_in, const int* in_sizes, int n_in,
                              void* d_out, int out_size)
{
    const float* x       = (const float*)d_in[0];
    const int*   ei      = (const int*)  d_in[1];
    const int*   batch   = (const int*)  d_in[2];
    const float* w1_rel  = (const float*)d_in[3];
    const float* w1_root = (const float*)d_in[4];
    const float* b1      = (const float*)d_in[5];
    const float* w_rel   = (const float*)d_in[6];   // [4,100,100]
    const float* w_root  = (const float*)d_in[7];   // [4,100,100]
    const float* bb      = (const float*)d_in[8];   // [4,100]
    const float* lw1     = (const float*)d_in[9];
    const float* lb1     = (const float*)d_in[10];
    const float* lw2     = (const float*)d_in[11];
    const float* lb2     = (const float*)d_in[12];
    const float* lw3     = (const float*)d_in[13];
    const float* lb3     = (const float*)d_in[14];
    float* out = (float*)d_out;

    const int* src = ei;
    const int* dst = ei + NEDGES;

    float *yrel, *buf0, *buf1, *pool, *m1, *m2;
    cudaGetSymbolAddress((void**)&yrel, g_yrel);
    cudaGetSymbolAddress((void**)&buf0, g_buf0);
    cudaGetSymbolAddress((void**)&buf1, g_buf1);
    cudaGetSymbolAddress((void**)&pool, g_pool);
    cudaGetSymbolAddress((void**)&m1,   g_m1);
    cudaGetSymbolAddress((void**)&m2,   g_m2);

    dim3 gemm_grid((NNODES + BM - 1) / BM, 2);
    int scat_blocks = (NEDGES * 32 + 255) / 256;

    // Layer 1: x [N,336] -> buf0 (pre-relu)
    gemm_dual<<<gemm_grid, 256>>>(x, NNODES, K1, w1_rel, w1_root, b1,
                                  yrel, buf0, 0);
    scatter_edges<<<scat_blocks, 256>>>(src, dst, yrel, buf0);

    // Layers 2..5: relu folded into GEMM load; ping-pong buffers
    float* bufs[2] = { buf0, buf1 };
    for (int l = 0; l < 4; l++) {
        float* bin  = bufs[l & 1];
        float* bout = bufs[(l + 1) & 1];
        gemm_dual<<<gemm_grid, 256>>>(bin, NNODES, HID,
                                      w_rel + (size_t)l * HID * HID,
                                      w_root + (size_t)l * HID * HID,
                                      bb + l * HID,
                                      yrel, bout, 1);
        scatter_edges<<<scat_blocks, 256>>>(src, dst, yrel, bout);
    }
    // Final conv output (pre-relu) is in buf0 (l=3 wrote bufs[0]).

    pool_kernel<<<NGRAPHS, 128>>>(buf0, batch, pool);
    mlp_kernel<<<NGRAPHS, 128>>>(pool, lw1, lb1, m1, HID, HID, 1);
    mlp_kernel<<<NGRAPHS, 128>>>(m1,   lw2, lb2, m2, HID, HID, 1);
    mlp_kernel<<<NGRAPHS, 128>>>(m2,   lw3, lb3, out, HID, NOUT, 0);
}

// round 2
// speedup vs baseline: 1.4524x; 1.4524x over previous
#include <cuda_runtime.h>

// Problem constants (fixed-shape problem)
#define NNODES 50000
#define NEDGES 800000
#define NGRAPHS 256
#define HID 100
#define K1 336
#define NOUT 29

// Scratch (device globals — allocation-free rule)
__device__ float g_yrel[NNODES * HID];
__device__ float g_buf0[NNODES * HID];
__device__ float g_buf1[NNODES * HID];
__device__ float g_pool[NGRAPHS * HID];
__device__ float g_m1[NGRAPHS * HID];
__device__ float g_m2[NGRAPHS * HID];

// CSR scratch
__device__ int g_cnt[NNODES];
__device__ int g_cur[NNODES];
__device__ int g_offs[NNODES + 1];
__device__ int g_csr_src[NEDGES];
#define SCAN_B 512
#define NSCAN ((NNODES + SCAN_B - 1) / SCAN_B)   // 98
__device__ int g_bsum[NSCAN];

// ---------------------------------------------------------------------------
// CSR build: count -> scan (two-level) -> fill
// ---------------------------------------------------------------------------
__global__ __launch_bounds__(256) void csr_zero() {
    int i = blockIdx.x * blockDim.x + threadIdx.x;
    if (i < NNODES) { g_cnt[i] = 0; g_cur[i] = 0; }
    if (i == 0) g_offs[0] = 0;
}

__global__ __launch_bounds__(256) void csr_count(const int* __restrict__ dst) {
    int e = blockIdx.x * blockDim.x + threadIdx.x;
    if (e < NEDGES) atomicAdd(&g_cnt[dst[e]], 1);
}

__global__ __launch_bounds__(SCAN_B) void csr_scan_local() {
    __shared__ int sh[SCAN_B];
    int tid = threadIdx.x;
    int idx = blockIdx.x * SCAN_B + tid;
    int v = (idx < NNODES) ? g_cnt[idx] : 0;
    sh[tid] = v;
    __syncthreads();
#pragma unroll
    for (int d = 1; d < SCAN_B; d <<= 1) {
        int t = (tid >= d) ? sh[tid - d] : 0;
        __syncthreads();
        sh[tid] += t;
        __syncthreads();
    }
    if (idx < NNODES) g_offs[idx + 1] = sh[tid];
    if (tid == SCAN_B - 1) g_bsum[blockIdx.x] = sh[tid];
}

__global__ __launch_bounds__(128) void csr_scan_bsums() {
    __shared__ int sh[128];
    int tid = threadIdx.x;
    sh[tid] = (tid < NSCAN) ? g_bsum[tid] : 0;
    __syncthreads();
#pragma unroll
    for (int d = 1; d < 128; d <<= 1) {
        int t = (tid >= d) ? sh[tid - d] : 0;
        __syncthreads();
        sh[tid] += t;
        __syncthreads();
    }
    // write exclusive
    if (tid < NSCAN) g_bsum[tid] = (tid == 0) ? 0 : sh[tid - 1];
}

__global__ __launch_bounds__(256) void csr_scan_add() {
    int idx = blockIdx.x * blockDim.x + threadIdx.x;
    if (idx < NNODES) g_offs[idx + 1] += g_bsum[idx / SCAN_B];
}

__global__ __launch_bounds__(256) void csr_fill(const int* __restrict__ src,
                                                const int* __restrict__ dst) {
    int e = blockIdx.x * blockDim.x + threadIdx.x;
    if (e < NEDGES) {
        int d = dst[e];
        int pos = g_offs[d] + atomicAdd(&g_cur[d], 1);
        g_csr_src[pos] = src[e];
    }
}

// ---------------------------------------------------------------------------
// Gather aggregate: out[node,:] += sum_{e in csr[node]} yrel[src_e,:]
// Warp per node, float4 lanes; no atomics.
// ---------------------------------------------------------------------------
__global__ __launch_bounds__(256) void gather_add(
    const float* __restrict__ yrel, float* __restrict__ out)
{
    int node = blockIdx.x * 8 + (threadIdx.x >> 5);
    int lane = threadIdx.x & 31;
    if (node >= NNODES || lane >= HID / 4) return;
    int beg = g_offs[node];
    int end = g_offs[node + 1];
    const float4* base = (const float4*)yrel;
    float4* op = (float4*)(out + (size_t)node * HID);
    float4 acc = op[lane];  // root + bias already there
    int e = beg;
    for (; e + 1 < end; e += 2) {
        int s0 = g_csr_src[e];
        int s1 = g_csr_src[e + 1];
        float4 v0 = base[(size_t)s0 * (HID / 4) + lane];
        float4 v1 = base[(size_t)s1 * (HID / 4) + lane];
        acc.x += v0.x + v1.x;
        acc.y += v0.y + v1.y;
        acc.z += v0.z + v1.z;
        acc.w += v0.w + v1.w;
    }
    if (e < end) {
        int s0 = g_csr_src[e];
        float4 v0 = base[(size_t)s0 * (HID / 4) + lane];
        acc.x += v0.x; acc.y += v0.y; acc.z += v0.z; acc.w += v0.w;
    }
    op[lane] = acc;
}

// ---------------------------------------------------------------------------
// Dual GEMM 128x128x8, 8x8 register tiles, float4 LDS.
//   blockIdx.y==0: Yrel = act(A) @ Wrel.T
//   blockIdx.y==1: Agg  = act(A) @ Wroot.T + bias
// ---------------------------------------------------------------------------
#define GBM 128
#define GBN 128
#define GBK 8

__global__ __launch_bounds__(256) void gemm_dual(
    const float* __restrict__ A, int K,
    const float* __restrict__ Wrel, const float* __restrict__ Wroot,
    const float* __restrict__ bias,
    float* __restrict__ Yrel, float* __restrict__ Agg, int applyRelu)
{
    const float* W = blockIdx.y ? Wroot : Wrel;
    float* O = blockIdx.y ? Agg : Yrel;
    const int addB = blockIdx.y;

    __shared__ float As[GBK][GBM + 4];
    __shared__ float Bs[GBK][GBN + 4];

    const int tid = threadIdx.x;
    const int tx = tid & 15;     // n-group (8 cols)
    const int ty = tid >> 4;     // m-group (8 rows)
    const int row0 = blockIdx.x * GBM;
    const int lm = tid >> 1;         // 0..127
    const int lk = (tid & 1) * 4;    // 0 or 4

    float acc[8][8];
#pragma unroll
    for (int i = 0; i < 8; i++)
#pragma unroll
        for (int j = 0; j < 8; j++) acc[i][j] = 0.f;

    const int kiters = (K + GBK - 1) / GBK;
    for (int it = 0; it < kiters; it++) {
        const int k0 = it * GBK;
        // Load A tile: 128 rows x 8 k (1 float4/thread)
        {
            int r = row0 + lm;
            float4 v = make_float4(0.f, 0.f, 0.f, 0.f);
            if (r < NNODES && (k0 + lk + 3) < K)
                v = *(const float4*)(A + (size_t)r * K + k0 + lk);
            if (applyRelu) {
                v.x = fmaxf(v.x, 0.f); v.y = fmaxf(v.y, 0.f);
                v.z = fmaxf(v.z, 0.f); v.w = fmaxf(v.w, 0.f);
            }
            As[lk + 0][lm] = v.x; As[lk + 1][lm] = v.y;
            As[lk + 2][lm] = v.z; As[lk + 3][lm] = v.w;
        }
        // Load W tile transposed: Bs[k][n] = W[n, k0+k]
        {
            float4 v = make_float4(0.f, 0.f, 0.f, 0.f);
            if (lm < HID && (k0 + lk + 3) < K)
                v = *(const float4*)(W + (size_t)lm * K + k0 + lk);
            Bs[lk + 0][lm] = v.x; Bs[lk + 1][lm] = v.y;
            Bs[lk + 2][lm] = v.z; Bs[lk + 3][lm] = v.w;
        }
        __syncthreads();

#pragma unroll
        for (int k = 0; k < GBK; k++) {
            float a[8], b[8];
            *(float4*)(a)     = *(const float4*)&As[k][ty * 8];
            *(float4*)(a + 4) = *(const float4*)&As[k][ty * 8 + 4];
            *(float4*)(b)     = *(const float4*)&Bs[k][tx * 8];
            *(float4*)(b + 4) = *(const float4*)&Bs[k][tx * 8 + 4];
#pragma unroll
            for (int i = 0; i < 8; i++)
#pragma unroll
                for (int j = 0; j < 8; j++)
                    acc[i][j] = fmaf(a[i], b[j], acc[i][j]);
        }
        __syncthreads();
    }

#pragma unroll
    for (int i = 0; i < 8; i++) {
        int r = row0 + ty * 8 + i;
        if (r >= NNODES) continue;
#pragma unroll
        for (int j = 0; j < 8; j++) {
            int n = tx * 8 + j;
            if (n < HID) {
                float v = acc[i][j];
                if (addB) v += bias[n];
                O[(size_t)r * HID + n] = v;
            }
        }
    }
}

// ---------------------------------------------------------------------------
// Mean pool over sorted batch (relu folded in)
// ---------------------------------------------------------------------------
__device__ __forceinline__ int lower_bound_i(const int* a, int n, int key) {
    int lo = 0, hi = n;
    while (lo < hi) {
        int mid = (lo + hi) >> 1;
        if (a[mid] < key) lo = mid + 1; else hi = mid;
    }
    return lo;
}

__global__ __launch_bounds__(128) void pool_kernel(
    const float* __restrict__ h, const int* __restrict__ batch,
    float* __restrict__ pooled)
{
    int g = blockIdx.x;
    __shared__ int s_se[2];
    if (threadIdx.x == 0) {
        s_se[0] = lower_bound_i(batch, NNODES, g);
        s_se[1] = lower_bound_i(batch, NNODES, g + 1);
    }
    __syncthreads();
    int start = s_se[0], end = s_se[1];
    int c = threadIdx.x;
    if (c < HID) {
        float s = 0.f;
        for (int i = start; i < end; i++)
            s += fmaxf(h[(size_t)i * HID + c], 0.f);
        float cnt = (float)((end - start) > 0 ? (end - start) : 1);
        pooled[g * HID + c] = s / cnt;
    }
}

// ---------------------------------------------------------------------------
// Small MLP layer
// ---------------------------------------------------------------------------
__global__ __launch_bounds__(128) void mlp_kernel(
    const float* __restrict__ in, const float* __restrict__ W,
    const float* __restrict__ bv, float* __restrict__ out,
    int Kin, int Nout, int doRelu)
{
    int g = blockIdx.x;
    __shared__ float sin_[128];
    if (threadIdx.x < Kin) sin_[threadIdx.x] = in[g * Kin + threadIdx.x];
    __syncthreads();
    int c = threadIdx.x;
    if (c < Nout) {
        float s = bv[c];
        const float* wr = W + (size_t)c * Kin;
        for (int k = 0; k < Kin; k++) s = fmaf(sin_[k], wr[k], s);
        if (doRelu) s = fmaxf(s, 0.f);
        out[g * Nout + c] = s;
    }
}

// ---------------------------------------------------------------------------
extern "C" void kernel_launch(void* const* d_in, const int* in_sizes, int n_in,
                              void* d_out, int out_size)
{
    const float* x       = (const float*)d_in[0];
    const int*   ei      = (const int*)  d_in[1];
    const int*   batch   = (const int*)  d_in[2];
    const float* w1_rel  = (const float*)d_in[3];
    const float* w1_root = (const float*)d_in[4];
    const float* b1      = (const float*)d_in[5];
    const float* w_rel   = (const float*)d_in[6];   // [4,100,100]
    const float* w_root  = (const float*)d_in[7];   // [4,100,100]
    const float* bb      = (const float*)d_in[8];   // [4,100]
    const float* lw1     = (const float*)d_in[9];
    const float* lb1     = (const float*)d_in[10];
    const float* lw2     = (const float*)d_in[11];
    const float* lb2     = (const float*)d_in[12];
    const float* lw3     = (const float*)d_in[13];
    const float* lb3     = (const float*)d_in[14];
    float* out = (float*)d_out;

    const int* src = ei;
    const int* dst = ei + NEDGES;

    float *yrel, *buf0, *buf1, *pool, *m1, *m2;
    cudaGetSymbolAddress((void**)&yrel, g_yrel);
    cudaGetSymbolAddress((void**)&buf0, g_buf0);
    cudaGetSymbolAddress((void**)&buf1, g_buf1);
    cudaGetSymbolAddress((void**)&pool, g_pool);
    cudaGetSymbolAddress((void**)&m1,   g_m1);
    cudaGetSymbolAddress((void**)&m2,   g_m2);

    // --- CSR build (once per launch, deterministic work) ---
    csr_zero<<<(NNODES + 255) / 256, 256>>>();
    csr_count<<<(NEDGES + 255) / 256, 256>>>(dst);
    csr_scan_local<<<NSCAN, SCAN_B>>>();
    csr_scan_bsums<<<1, 128>>>();
    csr_scan_add<<<(NNODES + 255) / 256, 256>>>();
    csr_fill<<<(NEDGES + 255) / 256, 256>>>(src, dst);

    dim3 gemm_grid((NNODES + GBM - 1) / GBM, 2);
    int gat_blocks = (NNODES + 7) / 8;

    // Layer 1: x [N,336]
    gemm_dual<<<gemm_grid, 256>>>(x, K1, w1_rel, w1_root, b1, yrel, buf0, 0);
    gather_add<<<gat_blocks, 256>>>(yrel, buf0);

    // Layers 2..5 (relu folded into GEMM A-load)
    float* bufs[2] = { buf0, buf1 };
    for (int l = 0; l < 4; l++) {
        float* bin  = bufs[l & 1];
        float* bout = bufs[(l + 1) & 1];
        gemm_dual<<<gemm_grid, 256>>>(bin, HID,
                                      w_rel + (size_t)l * HID * HID,
                                      w_root + (size_t)l * HID * HID,
                                      bb + l * HID,
                                      yrel, bout, 1);
        gather_add<<<gat_blocks, 256>>>(yrel, bout);
    }
    // Final conv output (pre-relu) is in buf0.

    pool_kernel<<<NGRAPHS, 128>>>(buf0, batch, pool);
    mlp_kernel<<<NGRAPHS, 128>>>(pool, lw1, lb1, m1, HID, HID, 1);
    mlp_kernel<<<NGRAPHS, 128>>>(m1,   lw2, lb2, m2, HID, HID, 1);
    mlp_kernel<<<NGRAPHS, 128>>>(m2,   lw3, lb3, out, HID, NOUT, 0);
}